// round 9
// baseline (speedup 1.0000x reference)
#include <cuda_runtime.h>
#include <math.h>

// Accumulators: [0]=cusp_same, [1]=cusp_diff, [2]=mlp_same, [3]=mlp_diff,
//               [4]=emb_out0_sum (excl. be2), [5]=emb_out1_sum (excl. be2)
__device__ double g_acc[8];

// ---------------------------------------------------------------------------
// helpers
// ---------------------------------------------------------------------------
__device__ __forceinline__ float tanh_approx(float x) {
    float y;
    asm("tanh.approx.f32 %0, %1;" : "=f"(y) : "f"(x));
    return y;
}

__device__ __forceinline__ unsigned long long pack2(float x) {
    unsigned long long r;
    unsigned u = __float_as_uint(x);
    asm("mov.b64 %0, {%1, %1};" : "=l"(r) : "r"(u));
    return r;
}

__device__ __forceinline__ unsigned long long ffma2(unsigned long long a,
                                                    unsigned long long b,
                                                    unsigned long long c) {
    unsigned long long d;
    asm("fma.rn.f32x2 %0, %1, %2, %3;" : "=l"(d) : "l"(a), "l"(b), "l"(c));
    return d;
}

__device__ __forceinline__ void unpack2(unsigned long long v, float& lo, float& hi) {
    unsigned a, b;
    asm("mov.b64 {%0, %1}, %2;" : "=r"(a), "=r"(b) : "l"(v));
    lo = __uint_as_float(a);
    hi = __uint_as_float(b);
}

__device__ __forceinline__ float softplus_f(float x) {
    if (x > 20.0f) return x;
    return log1pf(expf(x));
}

// ---------------------------------------------------------------------------
// init: zero accumulators
// ---------------------------------------------------------------------------
__global__ void init_kernel() {
    if (threadIdx.x < 8) g_acc[threadIdx.x] = 0.0;
}

// ---------------------------------------------------------------------------
// Fused kernel.
// Pair role (blockIdx.y < 128): block = (j-chunk of 128) x (8 consecutive i).
//   j = blockIdx.x*128 + threadIdx.x,  i in [blockIdx.y*8, blockIdx.y*8+8).
//   Spin-uniform per block (512 % 8 == 0, 128 | 512).
// Emb role (blockIdx.y >= 128): 32 blocks, each runs the 256->64->64->2 MLP
//   over 32 embedding rows (2 rows x 64 threads per iteration), accumulating
//   sum(h1 @ We2) into g_acc[4..5]; the +be2-per-row term is added in fin.
// ---------------------------------------------------------------------------
#define I_PER_BLOCK 8
#define PAIR_Y 128   // 1024 / I_PER_BLOCK
#define EMB_Y  4     // 8 * 4 = 32 emb blocks

__global__ void __launch_bounds__(128)
fused_kernel(const float* __restrict__ electrons,
             const float* __restrict__ A_same_p, const float* __restrict__ A_diff_p,
             const float* __restrict__ W0s, const float* __restrict__ b0s,
             const float* __restrict__ W1s, const float* __restrict__ b1s,
             const float* __restrict__ W2s,
             const float* __restrict__ W0d, const float* __restrict__ b0d,
             const float* __restrict__ W1d, const float* __restrict__ b1d,
             const float* __restrict__ W2d,
             const float* __restrict__ emb,
             const float* __restrict__ We0, const float* __restrict__ be0,
             const float* __restrict__ We1, const float* __restrict__ be1,
             const float* __restrict__ We2)
{
    __shared__ __align__(16) float sW1[64 * 64];
    __shared__ __align__(16) float sW0[4 * 64];
    __shared__ __align__(16) float sb0[64];
    __shared__ __align__(16) float sb1[64];
    __shared__ __align__(16) float sW2[64];
    __shared__ float sI[3 * I_PER_BLOCK];
    __shared__ float sE[2][64];
    __shared__ double sred[8];

    const int t = threadIdx.x;

    // ======================= EMB ROLE =======================
    if (blockIdx.y >= PAIR_Y) {
        const int eb   = (blockIdx.y - PAIR_Y) * 8 + blockIdx.x;  // 0..31
        const int half = t >> 6;   // row within the 2-row group
        const int o    = t & 63;   // output neuron

        double v0 = 0.0, v1 = 0.0;
        const float w2a = __ldg(&We2[o * 2 + 0]);
        const float w2b = __ldg(&We2[o * 2 + 1]);
        const float bb0 = __ldg(&be0[o]);
        const float bb1 = __ldg(&be1[o]);

        for (int it = 0; it < 16; ++it) {
            const int r = eb * 32 + 2 * it + half;   // 0..1023
            const float* erow = emb + r * 256;

            float acc = bb0;
#pragma unroll 8
            for (int k = 0; k < 256; ++k)
                acc = fmaf(__ldg(&erow[k]), __ldg(&We0[k * 64 + o]), acc);
            sE[half][o] = tanh_approx(acc);
            __syncthreads();

            float acc1 = bb1;
#pragma unroll 8
            for (int k = 0; k < 64; ++k)
                acc1 = fmaf(sE[half][k], __ldg(&We1[k * 64 + o]), acc1);
            const float h1 = tanh_approx(acc1);

            v0 += (double)(h1 * w2a);
            v1 += (double)(h1 * w2b);
            __syncthreads();  // protect sE for next iteration
        }

#pragma unroll
        for (int off = 16; off > 0; off >>= 1) {
            v0 += __shfl_down_sync(0xffffffffu, v0, off);
            v1 += __shfl_down_sync(0xffffffffu, v1, off);
        }
        const int w = t >> 5, l = t & 31;
        if (l == 0) { sred[w] = v0; sred[4 + w] = v1; }
        __syncthreads();
        if (t == 0) {
            atomicAdd(&g_acc[4], sred[0] + sred[1] + sred[2] + sred[3]);
            atomicAdd(&g_acc[5], sred[4] + sred[5] + sred[6] + sred[7]);
        }
        return;
    }

    // ======================= PAIR ROLE =======================
    const int i0 = blockIdx.y * I_PER_BLOCK;
    const int j  = blockIdx.x * 128 + t;
    const bool same = ((i0 < 512) == (blockIdx.x < 4));

    const float* W0 = same ? W0s : W0d;
    const float* b0 = same ? b0s : b0d;
    const float* W1 = same ? W1s : W1d;
    const float* b1 = same ? b1s : b1d;
    const float* W2 = same ? W2s : W2d;

    // cooperative weight staging; cudaMalloc'd inputs are >=256B aligned so
    // float4 loads of the 4096-float W1 are safe.
    {
        const float4* W1v = (const float4*)W1;
        float4*       sW1v = (float4*)sW1;
        for (int k = t; k < 1024; k += 128) sW1v[k] = W1v[k];
        const float4* W0v = (const float4*)W0;
        float4*       sW0v = (float4*)sW0;
        if (t < 64) sW0v[t] = W0v[t];
        if (t < 64)  sb0[t] = b0[t];
        else sb1[t - 64] = b1[t - 64];
        if (t < 16) ((float4*)sW2)[t] = ((const float4*)W2)[t];
        if (t < 3 * I_PER_BLOCK) sI[t] = electrons[3 * i0 + t];
    }
    __syncthreads();

    const float Ap = same ? A_same_p[0] : A_diff_p[0];
    const float As = softplus_f(Ap);
    const float F  = sqrtf(2.0f * As);

    const float jx = electrons[3 * j + 0];
    const float jy = electrons[3 * j + 1];
    const float jz = electrons[3 * j + 2];

    double dc = 0.0, dm = 0.0;

    for (int ii = 0; ii < I_PER_BLOCK; ++ii) {
        const int i = i0 + ii;
        const bool valid = (i != j);

        float ex = sI[3 * ii + 0] - jx;
        float ey = sI[3 * ii + 1] - jy;
        float ez = sI[3 * ii + 2] - jz;
        if (!valid) { ex = 1.0f; ey = 0.0f; ez = 0.0f; }  // finite dummy

        const float r    = sqrtf(ex * ex + ey * ey + ez * ez);
        const float cusp = expm1f(-r / F) / r;

        const float lr = log1pf(r);
        const float sc = lr / r;
        const float x0 = ex * sc, x1 = ey * sc, x2 = ez * sc, x3 = lr;

        // ---- layer 0: 4 -> 64 ----
        float h0[64];
#pragma unroll
        for (int o = 0; o < 64; o += 4) {
            float4 bb = *(const float4*)&sb0[o];
            float4 w0 = *(const float4*)&sW0[0 * 64 + o];
            float4 w1 = *(const float4*)&sW0[1 * 64 + o];
            float4 w2 = *(const float4*)&sW0[2 * 64 + o];
            float4 w3 = *(const float4*)&sW0[3 * 64 + o];
            h0[o + 0] = tanh_approx(fmaf(x0, w0.x, fmaf(x1, w1.x, fmaf(x2, w2.x, fmaf(x3, w3.x, bb.x)))));
            h0[o + 1] = tanh_approx(fmaf(x0, w0.y, fmaf(x1, w1.y, fmaf(x2, w2.y, fmaf(x3, w3.y, bb.y)))));
            h0[o + 2] = tanh_approx(fmaf(x0, w0.z, fmaf(x1, w1.z, fmaf(x2, w2.z, fmaf(x3, w3.z, bb.z)))));
            h0[o + 3] = tanh_approx(fmaf(x0, w0.w, fmaf(x1, w1.w, fmaf(x2, w2.w, fmaf(x3, w3.w, bb.w)))));
        }

        // ---- layer 1 (64 -> 64) + layer 2 (64 -> 1), packed f32x2 ----
        float out = 0.0f;
        for (int c = 0; c < 4; ++c) {
            unsigned long long acc[8];
#pragma unroll
            for (int p = 0; p < 8; ++p)
                acc[p] = *(const unsigned long long*)&sb1[c * 16 + 2 * p];

            const float* wbase = &sW1[c * 16];
#pragma unroll
            for (int k = 0; k < 64; ++k) {
                const unsigned long long hh = pack2(h0[k]);
                const ulonglong2* wp = (const ulonglong2*)(wbase + k * 64);
                ulonglong2 wa = wp[0];
                ulonglong2 wb = wp[1];
                ulonglong2 wc = wp[2];
                ulonglong2 wd = wp[3];
                acc[0] = ffma2(hh, wa.x, acc[0]);
                acc[1] = ffma2(hh, wa.y, acc[1]);
                acc[2] = ffma2(hh, wb.x, acc[2]);
                acc[3] = ffma2(hh, wb.y, acc[3]);
                acc[4] = ffma2(hh, wc.x, acc[4]);
                acc[5] = ffma2(hh, wc.y, acc[5]);
                acc[6] = ffma2(hh, wd.x, acc[6]);
                acc[7] = ffma2(hh, wd.y, acc[7]);
            }
#pragma unroll
            for (int p = 0; p < 8; ++p) {
                float lo, hi;
                unpack2(acc[p], lo, hi);
                out = fmaf(tanh_approx(lo), sW2[c * 16 + 2 * p + 0], out);
                out = fmaf(tanh_approx(hi), sW2[c * 16 + 2 * p + 1], out);
            }
        }

        if (valid) { dc += (double)cusp; dm += (double)out; }
    }

    // ---- block reduction in double ----
#pragma unroll
    for (int off = 16; off > 0; off >>= 1) {
        dc += __shfl_down_sync(0xffffffffu, dc, off);
        dm += __shfl_down_sync(0xffffffffu, dm, off);
    }
    const int w = t >> 5, l = t & 31;
    if (l == 0) { sred[w] = dc; sred[4 + w] = dm; }
    __syncthreads();
    if (t == 0) {
        double c = sred[0] + sred[1] + sred[2] + sred[3];
        double m = sred[4] + sred[5] + sred[6] + sred[7];
        atomicAdd(&g_acc[same ? 0 : 1], c);
        atomicAdd(&g_acc[same ? 2 : 3], m);
    }
}

// ---------------------------------------------------------------------------
// Finalize: combine scalars -> (sign, logpsi).
// g_acc[4..5] exclude the per-row be2 term; add 1024*be2 here.
// ---------------------------------------------------------------------------
__global__ void fin_kernel(float* __restrict__ out,
                           const float* __restrict__ A_same_p,
                           const float* __restrict__ A_diff_p,
                           const float* __restrict__ scale_same,
                           const float* __restrict__ scale_diff,
                           const float* __restrict__ be2,
                           const float* __restrict__ mlp_scale,
                           const float* __restrict__ log_bias)
{
    if (threadIdx.x != 0 || blockIdx.x != 0) return;
    double As = (double)softplus_f(A_same_p[0]);
    double Ad = (double)softplus_f(A_diff_p[0]);

    double logpsi = As * g_acc[0] + Ad * g_acc[1]
                  + (double)scale_same[0] * g_acc[2]
                  + (double)scale_diff[0] * g_acc[3];

    double s4 = g_acc[4] + 1024.0 * (double)be2[0];
    double s5 = g_acc[5] + 1024.0 * (double)be2[1];

    double J0 = (double)mlp_scale[0] * s4;
    double J1 = (double)mlp_scale[1] * s5 + 1024.0 * (double)log_bias[0];

    float sign = (J1 > 0.0) ? 1.0f : ((J1 < 0.0) ? -1.0f : 0.0f);
    logpsi += J0 + log(fabs(J1));

    out[0] = sign;
    out[1] = (float)logpsi;
}

// ---------------------------------------------------------------------------
// launch
// ---------------------------------------------------------------------------
extern "C" void kernel_launch(void* const* d_in, const int* in_sizes, int n_in,
                              void* d_out, int out_size)
{
    const float* electrons  = (const float*)d_in[0];
    const float* embeddings = (const float*)d_in[1];
    const float* A_same     = (const float*)d_in[2];
    const float* A_diff     = (const float*)d_in[3];
    const float* Ws0_same   = (const float*)d_in[4];
    const float* bs0_same   = (const float*)d_in[5];
    const float* Ws1_same   = (const float*)d_in[6];
    const float* bs1_same   = (const float*)d_in[7];
    const float* Ws2_same   = (const float*)d_in[8];
    const float* Ws0_diff   = (const float*)d_in[9];
    const float* bs0_diff   = (const float*)d_in[10];
    const float* bs1_diff_W = (const float*)d_in[11]; // Ws1_diff
    const float* bs1_diff   = (const float*)d_in[12];
    const float* Ws2_diff   = (const float*)d_in[13];
    const float* scale_same = (const float*)d_in[14];
    const float* scale_diff = (const float*)d_in[15];
    const float* We0        = (const float*)d_in[16];
    const float* be0        = (const float*)d_in[17];
    const float* We1        = (const float*)d_in[18];
    const float* be1        = (const float*)d_in[19];
    const float* We2        = (const float*)d_in[20];
    const float* be2        = (const float*)d_in[21];
    const float* mlp_scale  = (const float*)d_in[22];
    const float* log_bias   = (const float*)d_in[23];

    init_kernel<<<1, 32>>>();

    fused_kernel<<<dim3(8, PAIR_Y + EMB_Y), 128>>>(
        electrons, A_same, A_diff,
        Ws0_same, bs0_same, Ws1_same, bs1_same, Ws2_same,
        Ws0_diff, bs0_diff, bs1_diff_W, bs1_diff, Ws2_diff,
        embeddings, We0, be0, We1, be1, We2);

    fin_kernel<<<1, 32>>>((float*)d_out, A_same, A_diff,
                          scale_same, scale_diff, be2, mlp_scale, log_bias);
}

// round 10
// speedup vs baseline: 2.1405x; 2.1405x over previous
#include <cuda_runtime.h>
#include <math.h>

// Accumulators: [0]=cusp_same, [1]=cusp_diff, [2]=mlp_same, [3]=mlp_diff,
//               [4]=emb_out0_sum (excl. be2), [5]=emb_out1_sum (excl. be2)
// Zero-initialized at module load; reset by the finalizing block each run.
__device__ double g_acc[8];
__device__ unsigned int g_done;

#define I_PER_BLOCK 8
#define PAIR_Y 128                    // 1024 / I_PER_BLOCK
#define EMB_Y  4                      // 8 * 4 = 32 emb blocks
#define TOTAL_BLOCKS (8 * (PAIR_Y + EMB_Y))

// ---------------------------------------------------------------------------
// helpers
// ---------------------------------------------------------------------------
__device__ __forceinline__ float tanh_approx(float x) {
    float y;
    asm("tanh.approx.f32 %0, %1;" : "=f"(y) : "f"(x));
    return y;
}

__device__ __forceinline__ unsigned long long pack2(float x) {
    unsigned long long r;
    unsigned u = __float_as_uint(x);
    asm("mov.b64 %0, {%1, %1};" : "=l"(r) : "r"(u));
    return r;
}

__device__ __forceinline__ unsigned long long ffma2(unsigned long long a,
                                                    unsigned long long b,
                                                    unsigned long long c) {
    unsigned long long d;
    asm("fma.rn.f32x2 %0, %1, %2, %3;" : "=l"(d) : "l"(a), "l"(b), "l"(c));
    return d;
}

__device__ __forceinline__ void unpack2(unsigned long long v, float& lo, float& hi) {
    unsigned a, b;
    asm("mov.b64 {%0, %1}, %2;" : "=r"(a), "=r"(b) : "l"(v));
    lo = __uint_as_float(a);
    hi = __uint_as_float(b);
}

__device__ __forceinline__ float softplus_f(float x) {
    if (x > 20.0f) return x;
    return log1pf(expf(x));
}

// ---------------------------------------------------------------------------
// Single fused kernel.
// Pair role (blockIdx.y < 128): block = (j-chunk of 128) x (8 consecutive i).
//   Phase 1: each thread computes features + layer0 (4->64) for its pair.
//   Phase 2: activations staged to shared (half-K at a time); register-blocked
//            GEMM: thread = 8 pairs x 8 outputs, 32 FFMA2 per k-iter.
//   Phase 3: tanh + W2 dot, deterministic cross-thread reduce via sP2.
// Emb role (blockIdx.y >= 128): 32 blocks run the 256->64->64->2 MLP over 32
//   embedding rows each, accumulating sum(h1 @ We2) (be2 added in finalize).
// Last block (completion counter) finalizes into out[0..1] and resets state.
// ---------------------------------------------------------------------------
__global__ void __launch_bounds__(128)
fused_kernel(const float* __restrict__ electrons,
             const float* __restrict__ A_same_p, const float* __restrict__ A_diff_p,
             const float* __restrict__ W0s, const float* __restrict__ b0s,
             const float* __restrict__ W1s, const float* __restrict__ b1s,
             const float* __restrict__ W2s,
             const float* __restrict__ W0d, const float* __restrict__ b0d,
             const float* __restrict__ W1d, const float* __restrict__ b1d,
             const float* __restrict__ W2d,
             const float* __restrict__ emb,
             const float* __restrict__ We0, const float* __restrict__ be0,
             const float* __restrict__ We1, const float* __restrict__ be1,
             const float* __restrict__ We2,
             const float* __restrict__ scale_same, const float* __restrict__ scale_diff,
             const float* __restrict__ be2,
             const float* __restrict__ mlp_scale, const float* __restrict__ log_bias,
             float* __restrict__ out)
{
    __shared__ __align__(16) float sW1[64 * 64];     // 16 KB  W1[k][o]
    __shared__ __align__(16) float sH[32 * 128];     // 16 KB  h[k'][pair] (half-K)
    __shared__ __align__(16) float sP2[8 * 128];     //  4 KB  partials [og][pair]
    __shared__ __align__(16) float sW0[4 * 64];
    __shared__ __align__(16) float sb0[64];
    __shared__ __align__(16) float sb1[64];
    __shared__ __align__(16) float sW2[64];
    __shared__ float sI[3 * I_PER_BLOCK];
    __shared__ float sE[2][64];
    __shared__ double sred[8];

    const int t = threadIdx.x;

    // ======================= EMB ROLE =======================
    if (blockIdx.y >= PAIR_Y) {
        const int eb   = (blockIdx.y - PAIR_Y) * 8 + blockIdx.x;  // 0..31
        const int half = t >> 6;
        const int o    = t & 63;

        double v0 = 0.0, v1 = 0.0;
        const float w2a = __ldg(&We2[o * 2 + 0]);
        const float w2b = __ldg(&We2[o * 2 + 1]);
        const float bb0 = __ldg(&be0[o]);
        const float bb1 = __ldg(&be1[o]);

        for (int it = 0; it < 16; ++it) {
            const int r = eb * 32 + 2 * it + half;
            const float* erow = emb + r * 256;

            float acc = bb0;
#pragma unroll 8
            for (int k = 0; k < 256; ++k)
                acc = fmaf(__ldg(&erow[k]), __ldg(&We0[k * 64 + o]), acc);
            sE[half][o] = tanh_approx(acc);
            __syncthreads();

            float acc1 = bb1;
#pragma unroll 8
            for (int k = 0; k < 64; ++k)
                acc1 = fmaf(sE[half][k], __ldg(&We1[k * 64 + o]), acc1);
            const float h1 = tanh_approx(acc1);

            v0 += (double)(h1 * w2a);
            v1 += (double)(h1 * w2b);
            __syncthreads();
        }

#pragma unroll
        for (int off = 16; off > 0; off >>= 1) {
            v0 += __shfl_down_sync(0xffffffffu, v0, off);
            v1 += __shfl_down_sync(0xffffffffu, v1, off);
        }
        const int w = t >> 5, l = t & 31;
        if (l == 0) { sred[w] = v0; sred[4 + w] = v1; }
        __syncthreads();
        if (t == 0) {
            atomicAdd(&g_acc[4], sred[0] + sred[1] + sred[2] + sred[3]);
            atomicAdd(&g_acc[5], sred[4] + sred[5] + sred[6] + sred[7]);
        }
    } else {
        // ======================= PAIR ROLE =======================
        const int i0 = blockIdx.y * I_PER_BLOCK;
        const int j  = blockIdx.x * 128 + t;
        const bool same = ((i0 < 512) == (blockIdx.x < 4));

        const float* W0 = same ? W0s : W0d;
        const float* b0 = same ? b0s : b0d;
        const float* W1 = same ? W1s : W1d;
        const float* b1 = same ? b1s : b1d;
        const float* W2 = same ? W2s : W2d;

        // cooperative weight staging (float4; cudaMalloc'd inputs >=256B aligned)
        {
            const float4* W1v = (const float4*)W1;
            float4*       sW1v = (float4*)sW1;
            for (int k = t; k < 1024; k += 128) sW1v[k] = W1v[k];
            const float4* W0v = (const float4*)W0;
            float4*       sW0v = (float4*)sW0;
            if (t < 64) sW0v[t] = W0v[t];
            if (t < 64)  sb0[t] = b0[t];
            else sb1[t - 64] = b1[t - 64];
            if (t < 16) ((float4*)sW2)[t] = ((const float4*)W2)[t];
            if (t < 3 * I_PER_BLOCK) sI[t] = electrons[3 * i0 + t];
        }
        __syncthreads();

        const float Ap = same ? A_same_p[0] : A_diff_p[0];
        const float As = softplus_f(Ap);
        const float F  = sqrtf(2.0f * As);

        const float jx = electrons[3 * j + 0];
        const float jy = electrons[3 * j + 1];
        const float jz = electrons[3 * j + 2];

        const int pg = t & 15, og = t >> 4;
        const int p0 = pg * 8, o0 = og * 8;

        // pre-packed layer-1 biases for this thread's output tile
        unsigned long long bpk[8];
#pragma unroll
        for (int o = 0; o < 8; ++o) bpk[o] = pack2(sb1[o0 + o]);

        double dc = 0.0, dm = 0.0;

        for (int ii = 0; ii < I_PER_BLOCK; ++ii) {
            const int i = i0 + ii;
            const bool valid = (i != j);

            float ex = sI[3 * ii + 0] - jx;
            float ey = sI[3 * ii + 1] - jy;
            float ez = sI[3 * ii + 2] - jz;
            if (!valid) { ex = 1.0f; ey = 0.0f; ez = 0.0f; }

            const float r    = sqrtf(ex * ex + ey * ey + ez * ez);
            const float cusp = expm1f(-r / F) / r;

            const float lr = log1pf(r);
            const float sc = lr / r;
            const float x0 = ex * sc, x1 = ey * sc, x2 = ez * sc, x3 = lr;

            // ---- phase 1: layer 0 (4 -> 64) for this thread's pair ----
            float h0[64];
#pragma unroll
            for (int o = 0; o < 64; o += 4) {
                float4 bb = *(const float4*)&sb0[o];
                float4 w0 = *(const float4*)&sW0[0 * 64 + o];
                float4 w1 = *(const float4*)&sW0[1 * 64 + o];
                float4 w2 = *(const float4*)&sW0[2 * 64 + o];
                float4 w3 = *(const float4*)&sW0[3 * 64 + o];
                h0[o + 0] = tanh_approx(fmaf(x0, w0.x, fmaf(x1, w1.x, fmaf(x2, w2.x, fmaf(x3, w3.x, bb.x)))));
                h0[o + 1] = tanh_approx(fmaf(x0, w0.y, fmaf(x1, w1.y, fmaf(x2, w2.y, fmaf(x3, w3.y, bb.y)))));
                h0[o + 2] = tanh_approx(fmaf(x0, w0.z, fmaf(x1, w1.z, fmaf(x2, w2.z, fmaf(x3, w3.z, bb.z)))));
                h0[o + 3] = tanh_approx(fmaf(x0, w0.w, fmaf(x1, w1.w, fmaf(x2, w2.w, fmaf(x3, w3.w, bb.w)))));
            }

            // ---- phase 2: layer 1 (64 -> 64), register-blocked 8 pairs x 8 outs.
            // K split into two halves of 32 staged through sH (16 KB).
            unsigned long long acc[4][8];
#pragma unroll
            for (int pp = 0; pp < 4; ++pp)
#pragma unroll
                for (int o = 0; o < 8; ++o) acc[pp][o] = bpk[o];

#pragma unroll
            for (int half = 0; half < 2; ++half) {
#pragma unroll
                for (int kk = 0; kk < 32; ++kk)
                    sH[kk * 128 + t] = h0[half * 32 + kk];
                __syncthreads();

                const float* wbase = &sW1[half * 32 * 64];
#pragma unroll 8
                for (int kk = 0; kk < 32; ++kk) {
                    const ulonglong2* hp = (const ulonglong2*)&sH[kk * 128 + p0];
                    const ulonglong2 ha = hp[0];
                    const ulonglong2 hb = hp[1];
                    const float4* wv = (const float4*)&wbase[kk * 64 + o0];
                    const float4 wa = wv[0];
                    const float4 wb = wv[1];
                    unsigned long long w2p[8];
                    w2p[0] = pack2(wa.x); w2p[1] = pack2(wa.y);
                    w2p[2] = pack2(wa.z); w2p[3] = pack2(wa.w);
                    w2p[4] = pack2(wb.x); w2p[5] = pack2(wb.y);
                    w2p[6] = pack2(wb.z); w2p[7] = pack2(wb.w);
#pragma unroll
                    for (int o = 0; o < 8; ++o) {
                        acc[0][o] = ffma2(ha.x, w2p[o], acc[0][o]);
                        acc[1][o] = ffma2(ha.y, w2p[o], acc[1][o]);
                        acc[2][o] = ffma2(hb.x, w2p[o], acc[2][o]);
                        acc[3][o] = ffma2(hb.y, w2p[o], acc[3][o]);
                    }
                }
                __syncthreads();   // all reads of sH done before next half's stores
            }

            // ---- phase 3: tanh + W2 dot; deterministic cross-thread reduce ----
            float part[8];
#pragma unroll
            for (int p = 0; p < 8; ++p) part[p] = 0.0f;
#pragma unroll
            for (int pp = 0; pp < 4; ++pp) {
#pragma unroll
                for (int o = 0; o < 8; ++o) {
                    float lo, hi;
                    unpack2(acc[pp][o], lo, hi);
                    const float w2 = sW2[o0 + o];
                    part[2 * pp + 0] = fmaf(tanh_approx(lo), w2, part[2 * pp + 0]);
                    part[2 * pp + 1] = fmaf(tanh_approx(hi), w2, part[2 * pp + 1]);
                }
            }
#pragma unroll
            for (int p = 0; p < 8; ++p) sP2[og * 128 + p0 + p] = part[p];
            __syncthreads();

            float outv = 0.0f;
#pragma unroll
            for (int g = 0; g < 8; ++g) outv += sP2[g * 128 + t];

            if (valid) { dc += (double)cusp; dm += (double)outv; }
            __syncthreads();   // protect sP2/sH before next iteration's writes
        }

        // ---- block reduction in double ----
#pragma unroll
        for (int off = 16; off > 0; off >>= 1) {
            dc += __shfl_down_sync(0xffffffffu, dc, off);
            dm += __shfl_down_sync(0xffffffffu, dm, off);
        }
        const int w = t >> 5, l = t & 31;
        if (l == 0) { sred[w] = dc; sred[4 + w] = dm; }
        __syncthreads();
        if (t == 0) {
            double c = sred[0] + sred[1] + sred[2] + sred[3];
            double m = sred[4] + sred[5] + sred[6] + sred[7];
            atomicAdd(&g_acc[same ? 0 : 1], c);
            atomicAdd(&g_acc[same ? 2 : 3], m);
        }
    }

    // ======================= COMPLETION + FINALIZE =======================
    if (t == 0) {
        __threadfence();   // publish this block's g_acc contributions
        const unsigned int old = atomicAdd(&g_done, 1u);
        if (old == TOTAL_BLOCKS - 1) {
            __threadfence();   // acquire all blocks' g_acc writes

            const double As = (double)softplus_f(A_same_p[0]);
            const double Ad = (double)softplus_f(A_diff_p[0]);

            double logpsi = As * g_acc[0] + Ad * g_acc[1]
                          + (double)scale_same[0] * g_acc[2]
                          + (double)scale_diff[0] * g_acc[3];

            const double s4 = g_acc[4] + 1024.0 * (double)be2[0];
            const double s5 = g_acc[5] + 1024.0 * (double)be2[1];

            const double J0 = (double)mlp_scale[0] * s4;
            const double J1 = (double)mlp_scale[1] * s5 + 1024.0 * (double)log_bias[0];

            const float sign = (J1 > 0.0) ? 1.0f : ((J1 < 0.0) ? -1.0f : 0.0f);
            logpsi += J0 + log(fabs(J1));

            out[0] = sign;
            out[1] = (float)logpsi;

            // reset state for the next (graph-replayed) run
#pragma unroll
            for (int q = 0; q < 8; ++q) g_acc[q] = 0.0;
            __threadfence();
            g_done = 0u;
        }
    }
}

// ---------------------------------------------------------------------------
// launch
// ---------------------------------------------------------------------------
extern "C" void kernel_launch(void* const* d_in, const int* in_sizes, int n_in,
                              void* d_out, int out_size)
{
    const float* electrons  = (const float*)d_in[0];
    const float* embeddings = (const float*)d_in[1];
    const float* A_same     = (const float*)d_in[2];
    const float* A_diff     = (const float*)d_in[3];
    const float* Ws0_same   = (const float*)d_in[4];
    const float* bs0_same   = (const float*)d_in[5];
    const float* Ws1_same   = (const float*)d_in[6];
    const float* bs1_same   = (const float*)d_in[7];
    const float* Ws2_same   = (const float*)d_in[8];
    const float* Ws0_diff   = (const float*)d_in[9];
    const float* bs0_diff   = (const float*)d_in[10];
    const float* Ws1_diff   = (const float*)d_in[11];
    const float* bs1_diff   = (const float*)d_in[12];
    const float* Ws2_diff   = (const float*)d_in[13];
    const float* scale_same = (const float*)d_in[14];
    const float* scale_diff = (const float*)d_in[15];
    const float* We0        = (const float*)d_in[16];
    const float* be0        = (const float*)d_in[17];
    const float* We1        = (const float*)d_in[18];
    const float* be1        = (const float*)d_in[19];
    const float* We2        = (const float*)d_in[20];
    const float* be2        = (const float*)d_in[21];
    const float* mlp_scale  = (const float*)d_in[22];
    const float* log_bias   = (const float*)d_in[23];

    fused_kernel<<<dim3(8, PAIR_Y + EMB_Y), 128>>>(
        electrons, A_same, A_diff,
        Ws0_same, bs0_same, Ws1_same, bs1_same, Ws2_same,
        Ws0_diff, bs0_diff, Ws1_diff, bs1_diff, Ws2_diff,
        embeddings, We0, be0, We1, be1, We2,
        scale_same, scale_diff, be2, mlp_scale, log_bias,
        (float*)d_out);
}